// round 16
// baseline (speedup 1.0000x reference)
#include <cuda_runtime.h>
#include <cuda_bf16.h>
#include <math.h>
#include <stdint.h>

// Problem constants
#define BATCH 8
#define CH    512
#define SP    1024      // H*W = 32*32
#define NHEAD 8
#define HDIM  64
#define NGRP  32
#define GCH   16        // channels per group

// Scratch (device globals: allocation-free per harness rules)
__device__ __nv_bfloat16 g_h[BATCH * CH * SP];        // groupnorm out (bf16)
__device__ __nv_bfloat16 g_qkv[BATCH * 3 * CH * SP];  // qkv (bf16)
__device__ __nv_bfloat16 g_att[BATCH * CH * SP];      // attention out (bf16)
__device__ uint32_t g_winp[(3 * CH) * (CH / 2)];      // bf16 w_in  [M][K]
__device__ uint32_t g_woutp[CH * (CH / 2)];           // bf16 w_out [M][K]

// ---------------------------------------------------------------------------
// Helpers
// ---------------------------------------------------------------------------
__device__ __forceinline__ uint32_t pk(float lo, float hi) {
    uint32_t r;
    asm("cvt.rn.bf16x2.f32 %0, %1, %2;" : "=r"(r) : "f"(hi), "f"(lo));
    return r;
}

#define MMA_BF16(d, a, b0, b1)                                              \
    asm volatile(                                                           \
        "mma.sync.aligned.m16n8k16.row.col.f32.bf16.bf16.f32 "              \
        "{%0,%1,%2,%3}, {%4,%5,%6,%7}, {%8,%9}, {%0,%1,%2,%3};"             \
        : "+f"(d[0]), "+f"(d[1]), "+f"(d[2]), "+f"(d[3])                    \
        : "r"(a[0]), "r"(a[1]), "r"(a[2]), "r"(a[3]), "r"(b0), "r"(b1))

#define LDSM4(d, addr)                                                      \
    asm volatile("ldmatrix.sync.aligned.m8n8.x4.shared.b16 "                \
                 "{%0,%1,%2,%3}, [%4];"                                     \
                 : "=r"((d)[0]), "=r"((d)[1]), "=r"((d)[2]), "=r"((d)[3])   \
                 : "r"(addr))

#define LDSM4T(d, addr)                                                     \
    asm volatile("ldmatrix.sync.aligned.m8n8.x4.trans.shared.b16 "          \
                 "{%0,%1,%2,%3}, [%4];"                                     \
                 : "=r"((d)[0]), "=r"((d)[1]), "=r"((d)[2]), "=r"((d)[3])   \
                 : "r"(addr))

#define CPA16(dst, src)                                                     \
    asm volatile("cp.async.cg.shared.global [%0], [%1], 16;"                \
                 :: "r"(dst), "l"(src))
#define CPA_COMMIT() asm volatile("cp.async.commit_group;")
#define CPA_WAIT0()  asm volatile("cp.async.wait_group 0;" ::: "memory")

// ---------------------------------------------------------------------------
// Weight prepack: fp32 [M][K] -> bf16 [M][K]
// ---------------------------------------------------------------------------
__global__ __launch_bounds__(256) void prepack_kernel(
    const float* __restrict__ w, uint32_t* __restrict__ wp, int nwords) {
    int i = blockIdx.x * 256 + threadIdx.x;
    if (i < nwords) {
        float2 v = *(const float2*)&w[2 * i];
        wp[i] = pk(v.x, v.y);
    }
}

// ---------------------------------------------------------------------------
// GroupNorm: stats + normalize, writes h bf16. One block per (batch, group).
// ---------------------------------------------------------------------------
__global__ void gn_kernel(const float* __restrict__ x,
                          const float* __restrict__ gamma,
                          const float* __restrict__ beta,
                          uint32_t* __restrict__ hw_all) {
    int b = blockIdx.x >> 5;
    int g = blockIdx.x & 31;
    const float* xp = x + ((size_t)b * CH + g * GCH) * SP;
    uint32_t* hw = hw_all + (((size_t)b * CH + g * GCH) * SP >> 1);
    int t = threadIdx.x;

    float sum = 0.f, sq = 0.f;
    for (int i4 = t; i4 < GCH * SP / 4; i4 += 256) {
        float4 v = *(const float4*)(xp + i4 * 4);
        sum += v.x + v.y + v.z + v.w;
        sq  += v.x * v.x + v.y * v.y + v.z * v.z + v.w * v.w;
    }
    __shared__ float s1[256], s2[256];
    s1[t] = sum; s2[t] = sq;
    __syncthreads();
    for (int off = 128; off > 0; off >>= 1) {
        if (t < off) { s1[t] += s1[t + off]; s2[t] += s2[t + off]; }
        __syncthreads();
    }
    const float invN = 1.f / (GCH * SP);
    float mean = s1[0] * invN;
    float var  = s2[0] * invN - mean * mean;
    float inv  = rsqrtf(var + 1e-6f);

    for (int i4 = t; i4 < GCH * SP / 4; i4 += 256) {
        int c = i4 >> 8;
        float sc = inv * gamma[g * GCH + c];
        float sh = beta[g * GCH + c] - mean * sc;
        float4 v = *(const float4*)(xp + i4 * 4);
        uint2 u;
        u.x = pk(v.x * sc + sh, v.y * sc + sh);
        u.y = pk(v.z * sc + sh, v.w * sc + sh);
        *(uint2*)&hw[i4 * 2] = u;
    }
}

// ---------------------------------------------------------------------------
// Templated GEMM (both projections) — K-tile 64, cp.async double-buffered.
//   As: [m 128][k 64 halves] pitch 72 halves (36 words) -> non-trans ldmatrix
//   Bs: [k 64][n 128 halves] pitch 136 halves (68 words) -> trans ldmatrix
// smem: 2*(18432 + 17408) = 71680 B -> 2 CTAs/SM.
// ---------------------------------------------------------------------------
#define APW 36
#define BPW 68

template <int MODE>
__global__ __launch_bounds__(256, 2) void gemm_kernel(
    const uint32_t* __restrict__ Awp, const __nv_bfloat16* __restrict__ Bm,
    const float* __restrict__ bias, const float* __restrict__ resid,
    void* __restrict__ Cv, int M, int N, int K) {
    __shared__ uint32_t As[2][128 * APW];
    __shared__ uint32_t Bs[2][64 * BPW];

    int tid  = threadIdx.x;
    int warp = tid >> 5, lane = tid & 31;
    int gid = lane >> 2, tg = lane & 3;
    int g8 = lane >> 3, lr = lane & 7;
    int wm = (warp >> 1) * 32, wn = (warp & 1) * 64;
    int m0 = blockIdx.y * 128, n0 = blockIdx.x * 128;

    const uint32_t* Bw = (const uint32_t*)(Bm + (size_t)blockIdx.z * K * N);

    uint32_t asb[2] = {(uint32_t)__cvta_generic_to_shared(&As[0][0]),
                       (uint32_t)__cvta_generic_to_shared(&As[1][0])};
    uint32_t bsb[2] = {(uint32_t)__cvta_generic_to_shared(&Bs[0][0]),
                       (uint32_t)__cvta_generic_to_shared(&Bs[1][0])};

    int nt_ro = (g8 & 1) * 8 + lr;
    int nt_co = (g8 >> 1) * 8;
    uint32_t a_off[2];
#pragma unroll
    for (int mt = 0; mt < 2; mt++)
        a_off[mt] = ((wm + mt * 16 + nt_ro) * 72 + nt_co) * 2;

    float acc[2][8][4];
#pragma unroll
    for (int mt = 0; mt < 2; mt++)
#pragma unroll
        for (int nt = 0; nt < 8; nt++)
#pragma unroll
            for (int e = 0; e < 4; e++) acc[mt][nt][e] = 0.f;

    // One K-tile = A[128m][64k] (16 KB) + B[64k][128n] (16 KB): 8 CPA16/thread
    auto issue_tile = [&](int buf, int k0) {
#pragma unroll
        for (int l = 0; l < 4; l++) {
            int slot = tid + l * 256;            // 0..1023
            int row = slot >> 3, j = slot & 7;   // 128 rows x 8 16B-chunks
            CPA16(asb[buf] + (row * APW + j * 4) * 4,
                  &Awp[(size_t)(m0 + row) * (K >> 1) + ((k0 + j * 8) >> 1)]);
        }
#pragma unroll
        for (int l = 0; l < 4; l++) {
            int slot = tid + l * 256;            // 0..1023
            int kk2 = slot >> 4, n8 = (slot & 15) * 8, n4 = (slot & 15) * 4;
            CPA16(bsb[buf] + (kk2 * BPW + n4) * 4,
                  &Bw[((size_t)(k0 + kk2) * N + n0 + n8) >> 1]);
        }
        CPA_COMMIT();
    };

    issue_tile(0, 0);
    CPA_WAIT0();
    __syncthreads();

    for (int k0 = 0; k0 < K; k0 += 64) {
        int cur = (k0 >> 6) & 1;
        bool nxt = (k0 + 64) < K;
        if (nxt) issue_tile(cur ^ 1, k0 + 64);

#pragma unroll
        for (int kk = 0; kk < 4; kk++) {
            int kb = kk * 16;   // halves
            uint32_t af[2][4];
            LDSM4(af[0], asb[cur] + a_off[0] + kb * 2);
            LDSM4(af[1], asb[cur] + a_off[1] + kb * 2);
#pragma unroll
            for (int ntp = 0; ntp < 4; ntp++) {
                uint32_t bb[4];
                LDSM4T(bb, bsb[cur] +
                           ((kb + nt_ro) * 136 + wn + ntp * 16 + nt_co) * 2);
                MMA_BF16(acc[0][2 * ntp],     af[0], bb[0], bb[1]);
                MMA_BF16(acc[1][2 * ntp],     af[1], bb[0], bb[1]);
                MMA_BF16(acc[0][2 * ntp + 1], af[0], bb[2], bb[3]);
                MMA_BF16(acc[1][2 * ntp + 1], af[1], bb[2], bb[3]);
            }
        }
        CPA_WAIT0();
        __syncthreads();
    }

    if (MODE == 0) {
        __nv_bfloat16* Cp = (__nv_bfloat16*)Cv + (size_t)blockIdx.z * M * N;
#pragma unroll
        for (int mt = 0; mt < 2; mt++) {
            int r0 = m0 + wm + mt * 16 + gid;
            int r1 = r0 + 8;
            float bv0 = bias[r0], bv1 = bias[r1];
#pragma unroll
            for (int nt = 0; nt < 8; nt++) {
                int col = n0 + wn + nt * 8 + tg * 2;
                ((uint32_t*)Cp)[((size_t)r0 * N + col) >> 1] =
                    pk(acc[mt][nt][0] + bv0, acc[mt][nt][1] + bv0);
                ((uint32_t*)Cp)[((size_t)r1 * N + col) >> 1] =
                    pk(acc[mt][nt][2] + bv1, acc[mt][nt][3] + bv1);
            }
        }
    } else {
        float* Cp       = (float*)Cv + (size_t)blockIdx.z * M * N;
        const float* Rp = resid + (size_t)blockIdx.z * M * N;
#pragma unroll
        for (int mt = 0; mt < 2; mt++) {
            int r0 = m0 + wm + mt * 16 + gid;
            int r1 = r0 + 8;
            float bv0 = bias[r0], bv1 = bias[r1];
#pragma unroll
            for (int nt = 0; nt < 8; nt++) {
                int col = n0 + wn + nt * 8 + tg * 2;
                float2 v0, v1;
                v0.x = acc[mt][nt][0] + bv0; v0.y = acc[mt][nt][1] + bv0;
                v1.x = acc[mt][nt][2] + bv1; v1.y = acc[mt][nt][3] + bv1;
                float2 q0 = *(const float2*)&Rp[(size_t)r0 * N + col];
                float2 q1 = *(const float2*)&Rp[(size_t)r1 * N + col];
                v0.x += q0.x; v0.y += q0.y;
                v1.x += q1.x; v1.y += q1.y;
                *(float2*)&Cp[(size_t)r0 * N + col] = v0;
                *(float2*)&Cp[(size_t)r1 * N + col] = v1;
            }
        }
    }
}

// ---------------------------------------------------------------------------
// BF16 flash attention — 64-q tiles, 4 warps/CTA, 2 CTAs/SM (unchanged R15).
// ---------------------------------------------------------------------------
#define QSW 36   // qs pitch in words
#define KPW 68   // ks/vs/p_s pitch in words
#define ATTN_WORDS (64 * QSW + 4 * 64 * KPW + 64 * KPW)
#define ATTN_SMEM_BYTES (ATTN_WORDS * 4)

__global__ __launch_bounds__(128) void attn_bf16_kernel(
    const __nv_bfloat16* __restrict__ qkv, __nv_bfloat16* __restrict__ out) {
    extern __shared__ uint32_t smw[];
    uint32_t* qs  = smw;                        // 64 x 36
    uint32_t* ks0 = qs + 64 * QSW;
    uint32_t* ks1 = ks0 + 64 * KPW;
    uint32_t* vs0 = ks1 + 64 * KPW;
    uint32_t* vs1 = vs0 + 64 * KPW;
    uint32_t* p_s = vs1 + 64 * KPW;             // 64 x 68
    __shared__ float corr_s[4][16];
    __shared__ float l_s[4][16];

    int tid  = threadIdx.x;
    int warp = tid >> 5, lane = tid & 31;
    int gid = lane >> 2, tg = lane & 3;
    int g8 = lane >> 3, lr = lane & 7;
    int wm = warp * 16;
    int qt = blockIdx.x * 64;
    int hn = blockIdx.y, b = blockIdx.z;

    const __nv_bfloat16* qg = qkv + ((size_t)b * 3 * CH + hn * HDIM) * SP;
    const __nv_bfloat16* kg = qg + (size_t)CH * SP;
    const __nv_bfloat16* vg = kg + (size_t)CH * SP;
    __nv_bfloat16* og = out + ((size_t)b * CH + hn * HDIM) * SP;

    const float SC = 0.125f * 1.44269504088896f;

    uint32_t qsb = (uint32_t)__cvta_generic_to_shared(qs);
    uint32_t ksbu[2] = {(uint32_t)__cvta_generic_to_shared(ks0),
                        (uint32_t)__cvta_generic_to_shared(ks1)};
    uint32_t vsbu[2] = {(uint32_t)__cvta_generic_to_shared(vs0),
                        (uint32_t)__cvta_generic_to_shared(vs1)};

    int nt_ro = (g8 & 1) * 8 + lr;
    int nt_co = (g8 >> 1) * 8;
    int qa_ro = (g8 >> 1) * 8 + lr;
    int qa_co = (g8 & 1) * 8;

    const uint32_t* qw = (const uint32_t*)qg;
    const uint32_t* kw = (const uint32_t*)kg;
    const uint32_t* vw = (const uint32_t*)vg;

    auto issue_kv = [&](int buf, int kt) {
#pragma unroll
        for (int l = 0; l < 8; l++) {
            int slot = tid + l * 128;
            int row = slot >> 4, h8 = (slot & 15) * 8, w4 = (slot & 15) * 4;
            CPA16(ksbu[buf] + (row * KPW + w4) * 4,
                  &kw[((size_t)row * SP + kt + h8) >> 1]);
            CPA16(vsbu[buf] + (row * KPW + w4) * 4,
                  &vw[((size_t)row * SP + kt + h8) >> 1]);
        }
        CPA_COMMIT();
    };

#pragma unroll
    for (int l = 0; l < 4; l++) {
        int slot = tid + l * 128;
        int row = slot >> 3, j = slot & 7;
        CPA16(qsb + (row * QSW + j * 4) * 4,
              &qw[((size_t)row * SP + qt + j * 8) >> 1]);
    }
    issue_kv(0, 0);
    CPA_WAIT0();
    __syncthreads();

    float m_run0 = -INFINITY, m_run1 = -INFINITY;
    float l_run0 = 0.f, l_run1 = 0.f;

    float acc_o[4][2][4];
#pragma unroll
    for (int mt = 0; mt < 4; mt++)
#pragma unroll
        for (int nq = 0; nq < 2; nq++)
#pragma unroll
            for (int e = 0; e < 4; e++) acc_o[mt][nq][e] = 0.f;

    for (int it = 0; it < SP / 128; it++) {
        int cur = it & 1;
        bool nxt = it < SP / 128 - 1;
        if (nxt) issue_kv(cur ^ 1, (it + 1) * 128);

        float acc_s[16][4];
#pragma unroll
        for (int nt = 0; nt < 16; nt++)
#pragma unroll
            for (int e = 0; e < 4; e++) acc_s[nt][e] = 0.f;

#pragma unroll
        for (int cc = 0; cc < 4; cc++) {
            int cb = cc * 16;
            uint32_t af[4];
            LDSM4T(af, qsb + ((cb + qa_ro) * 72 + wm + qa_co) * 2);
#pragma unroll
            for (int ntp = 0; ntp < 8; ntp++) {
                uint32_t bb[4];
                LDSM4T(bb, ksbu[cur] +
                           ((cb + nt_ro) * 136 + ntp * 16 + nt_co) * 2);
                MMA_BF16(acc_s[2 * ntp],     af, bb[0], bb[1]);
                MMA_BF16(acc_s[2 * ntp + 1], af, bb[2], bb[3]);
            }
        }

        float mx0 = -INFINITY, mx1 = -INFINITY;
#pragma unroll
        for (int nt = 0; nt < 16; nt++) {
            acc_s[nt][0] *= SC; acc_s[nt][1] *= SC;
            acc_s[nt][2] *= SC; acc_s[nt][3] *= SC;
            mx0 = fmaxf(mx0, fmaxf(acc_s[nt][0], acc_s[nt][1]));
            mx1 = fmaxf(mx1, fmaxf(acc_s[nt][2], acc_s[nt][3]));
        }
        mx0 = fmaxf(mx0, __shfl_xor_sync(0xffffffffu, mx0, 1));
        mx0 = fmaxf(mx0, __shfl_xor_sync(0xffffffffu, mx0, 2));
        mx1 = fmaxf(mx1, __shfl_xor_sync(0xffffffffu, mx1, 1));
        mx1 = fmaxf(mx1, __shfl_xor_sync(0xffffffffu, mx1, 2));

        float mnew0 = fmaxf(m_run0, mx0);
        float mnew1 = fmaxf(m_run1, mx1);
        float corr0 = exp2f(m_run0 - mnew0);
        float corr1 = exp2f(m_run1 - mnew1);

        float ps0 = 0.f, ps1 = 0.f;
#pragma unroll
        for (int nt = 0; nt < 16; nt++) {
            float p0 = exp2f(acc_s[nt][0] - mnew0);
            float p1 = exp2f(acc_s[nt][1] - mnew0);
            float p2 = exp2f(acc_s[nt][2] - mnew1);
            float p3 = exp2f(acc_s[nt][3] - mnew1);
            ps0 += p0 + p1; ps1 += p2 + p3;
            p_s[(wm + gid) * KPW + nt * 4 + tg]     = pk(p0, p1);
            p_s[(wm + gid + 8) * KPW + nt * 4 + tg] = pk(p2, p3);
        }
        ps0 += __shfl_xor_sync(0xffffffffu, ps0, 1);
        ps0 += __shfl_xor_sync(0xffffffffu, ps0, 2);
        ps1 += __shfl_xor_sync(0xffffffffu, ps1, 1);
        ps1 += __shfl_xor_sync(0xffffffffu, ps1, 2);
        l_run0 = l_run0 * corr0 + ps0;
        l_run1 = l_run1 * corr1 + ps1;
        m_run0 = mnew0; m_run1 = mnew1;
        if (tg == 0) {
            corr_s[warp][gid] = corr0;
            corr_s[warp][gid + 8] = corr1;
        }
        __syncwarp();

#pragma unroll
        for (int nq = 0; nq < 2; nq++) {
            float cc0 = corr_s[warp][nq * 8 + 2 * tg];
            float cc1 = corr_s[warp][nq * 8 + 2 * tg + 1];
#pragma unroll
            for (int mt = 0; mt < 4; mt++) {
                acc_o[mt][nq][0] *= cc0; acc_o[mt][nq][1] *= cc1;
                acc_o[mt][nq][2] *= cc0; acc_o[mt][nq][3] *= cc1;
            }
        }

#pragma unroll
        for (int kc = 0; kc < 8; kc++) {
            int kb = kc * 16;
            uint32_t bq[2][2];
#pragma unroll
            for (int nq = 0; nq < 2; nq++) {
                bq[nq][0] = p_s[(wm + nq * 8 + gid) * KPW + (kb >> 1) + tg];
                bq[nq][1] = p_s[(wm + nq * 8 + gid) * KPW + (kb >> 1) + tg + 4];
            }
#pragma unroll
            for (int mt = 0; mt < 4; mt++) {
                uint32_t af[4];
                LDSM4(af, vsbu[cur] +
                          ((mt * 16 + nt_ro) * 136 + kb + nt_co) * 2);
                MMA_BF16(acc_o[mt][0], af, bq[0][0], bq[0][1]);
                MMA_BF16(acc_o[mt][1], af, bq[1][0], bq[1][1]);
            }
        }

        CPA_WAIT0();
        __syncthreads();
    }

    if (tg == 0) {
        l_s[warp][gid] = l_run0;
        l_s[warp][gid + 8] = l_run1;
    }
    __syncwarp();

#pragma unroll
    for (int nq = 0; nq < 2; nq++) {
        float il0 = 1.f / l_s[warp][nq * 8 + 2 * tg];
        float il1 = 1.f / l_s[warp][nq * 8 + 2 * tg + 1];
        int s = qt + wm + nq * 8 + 2 * tg;
#pragma unroll
        for (int mt = 0; mt < 4; mt++) {
            int c0r = mt * 16 + gid;
            ((uint32_t*)og)[((size_t)c0r * SP + s) >> 1] =
                pk(acc_o[mt][nq][0] * il0, acc_o[mt][nq][1] * il1);
            ((uint32_t*)og)[((size_t)(c0r + 8) * SP + s) >> 1] =
                pk(acc_o[mt][nq][2] * il0, acc_o[mt][nq][3] * il1);
        }
    }
}

// ---------------------------------------------------------------------------
extern "C" void kernel_launch(void* const* d_in, const int* in_sizes, int n_in,
                              void* d_out, int out_size) {
    const float* x     = (const float*)d_in[0];
    const float* gamma = (const float*)d_in[1];
    const float* beta  = (const float*)d_in[2];
    const float* w_in  = (const float*)d_in[3];
    const float* b_in  = (const float*)d_in[4];
    const float* w_out = (const float*)d_in[5];
    const float* b_out = (const float*)d_in[6];
    float* out = (float*)d_out;

    __nv_bfloat16 *h, *qkv, *att;
    uint32_t *winp, *woutp;
    cudaGetSymbolAddress((void**)&h,     g_h);
    cudaGetSymbolAddress((void**)&qkv,   g_qkv);
    cudaGetSymbolAddress((void**)&att,   g_att);
    cudaGetSymbolAddress((void**)&winp,  g_winp);
    cudaGetSymbolAddress((void**)&woutp, g_woutp);

    // 0. Weight prepack (bf16 row-major)
    prepack_kernel<<<(3 * CH * CH / 2 + 255) / 256, 256>>>(w_in, winp,
                                                           3 * CH * CH / 2);
    prepack_kernel<<<(CH * CH / 2 + 255) / 256, 256>>>(w_out, woutp,
                                                       CH * CH / 2);

    // 1. GroupNorm -> h bf16
    gn_kernel<<<BATCH * NGRP, 256>>>(x, gamma, beta, (uint32_t*)h);

    // 2. QKV projection (K-tile 64, cp.async)
    cudaFuncSetAttribute(gemm_kernel<0>, cudaFuncAttributeMaxDynamicSharedMemorySize, 0);
    gemm_kernel<0><<<dim3(SP / 128, (3 * CH) / 128, BATCH), 256>>>(
        winp, h, b_in, nullptr, qkv, 3 * CH, SP, CH);

    // 3. Attention (64-q tiles, 4 warps, 2 CTAs/SM)
    cudaFuncSetAttribute(attn_bf16_kernel, cudaFuncAttributeMaxDynamicSharedMemorySize,
                         ATTN_SMEM_BYTES);
    attn_bf16_kernel<<<dim3(SP / 64, NHEAD, BATCH), 128, ATTN_SMEM_BYTES>>>(qkv, att);

    // 4. Output projection + bias + residual (K-tile 64)
    gemm_kernel<1><<<dim3(SP / 128, CH / 128, BATCH), 256>>>(
        woutp, att, b_out, x, out, CH, SP, CH);
}